// round 4
// baseline (speedup 1.0000x reference)
#include <cuda_runtime.h>

// DynamicUpsamplingFilter:
//   x:       (1, 3, 25, 128, 128) float32          -> d_in[0]
//   filters: (1, 25, 16, 25, 128, 128) float32     -> d_in[1]
//   out:     (1, 48, 25, 128, 128) float32
// out[c*16+u, t, h, w] = sum_{a,b} x[c, t, h+a-2, w+b-2] * filters[a*5+b, u, t, h, w]
//
// R4: conflict-free shared-memory patch access.
// Per a-row each thread loads its 8-float window as two aligned float4 LDS.128
// (conflict-free), reused for all 5 b values (b+i <= 7). b- and u-loops fully
// unrolled; a-loop rolled (fits L0 I$). Filter loads/stores remain float4.

#define T_DIM 25
#define H_DIM 128
#define W_DIM 128
#define HW    (H_DIM * W_DIM)       // 16384
#define THW   (T_DIM * HW)          // 409600
#define C_IN  3
#define KH    5
#define KW    5
#define UPSQ  16
#define UG    4                     // u per thread

__global__ __launch_bounds__(128, 5)
void duf_kernel(const float* __restrict__ x,
                const float* __restrict__ f,
                float* __restrict__ out)
{
    const int tid = threadIdx.x;
    const int w4  = tid & 31;            // float4 index over w
    const int ug  = tid >> 5;            // u group: u = 4*ug + j
    const int w0  = w4 << 2;
    const int h = blockIdx.x & (H_DIM - 1);
    const int t = blockIdx.x >> 7;

    // x patch tile: 3 channels x 5 rows x (128 + 4) cols, zero halo in w.
    // Row length 132 floats (multiple of 4) keeps &sx[c][a][w0] 16B-aligned.
    __shared__ __align__(16) float sx[C_IN][KH][W_DIM + 4];

    if (tid < 2) {
        #pragma unroll
        for (int c = 0; c < C_IN; c++)
            #pragma unroll
            for (int a = 0; a < KH; a++) {
                sx[c][a][tid] = 0.0f;
                sx[c][a][W_DIM + 2 + tid] = 0.0f;
            }
    }

    // stage x rows h-2..h+2 for all 3 channels (tid = w index here)
    #pragma unroll
    for (int c = 0; c < C_IN; c++) {
        #pragma unroll
        for (int a = 0; a < KH; a++) {
            const int hh = h + a - 2;
            float v = 0.0f;
            if (hh >= 0 && hh < H_DIM)
                v = __ldg(&x[c * THW + t * HW + hh * W_DIM + tid]);
            sx[c][a][tid + 2] = v;
        }
    }
    __syncthreads();

    const int rowbase = t * HW + h * W_DIM;
    // filter pointer for (k=0, u=4*ug, this row, w0)
    const float4* fp = (const float4*)(f + (size_t)(ug * UG) * THW + rowbase + w0);

    float4 acc[C_IN][UG];
    #pragma unroll
    for (int c = 0; c < C_IN; c++)
        #pragma unroll
        for (int j = 0; j < UG; j++)
            acc[c][j] = make_float4(0.f, 0.f, 0.f, 0.f);

    #pragma unroll 1
    for (int a = 0; a < KH; a++) {
        // conflict-free window load: 8 floats per channel as two aligned float4
        float win[C_IN][8];
        #pragma unroll
        for (int c = 0; c < C_IN; c++) {
            const float4 lo = *(const float4*)&sx[c][a][w0];
            const float4 hi = *(const float4*)&sx[c][a][w0 + 4];
            win[c][0] = lo.x; win[c][1] = lo.y; win[c][2] = lo.z; win[c][3] = lo.w;
            win[c][4] = hi.x; win[c][5] = hi.y; win[c][6] = hi.z; win[c][7] = hi.w;
        }

        const float4* fa = fp + (size_t)(a * KW) * (UPSQ * THW / 4);

        #pragma unroll
        for (int b = 0; b < KW; b++) {
            const float4* fk = fa + (size_t)b * (UPSQ * THW / 4);
            float4 fv[UG];
            #pragma unroll
            for (int j = 0; j < UG; j++)
                fv[j] = __ldg(fk + (size_t)j * (THW / 4));

            #pragma unroll
            for (int c = 0; c < C_IN; c++) {
                const float p0 = win[c][b];
                const float p1 = win[c][b + 1];
                const float p2 = win[c][b + 2];
                const float p3 = win[c][b + 3];
                #pragma unroll
                for (int j = 0; j < UG; j++) {
                    acc[c][j].x = fmaf(p0, fv[j].x, acc[c][j].x);
                    acc[c][j].y = fmaf(p1, fv[j].y, acc[c][j].y);
                    acc[c][j].z = fmaf(p2, fv[j].z, acc[c][j].z);
                    acc[c][j].w = fmaf(p3, fv[j].w, acc[c][j].w);
                }
            }
        }
    }

    // out[(c*16 + 4*ug + j)*THW + rowbase + w0], 512B/warp stores
    float4* op = (float4*)(out + (size_t)(ug * UG) * THW + rowbase + w0);
    #pragma unroll
    for (int c = 0; c < C_IN; c++)
        #pragma unroll
        for (int j = 0; j < UG; j++)
            op[((size_t)c * UPSQ + j) * (THW / 4)] = acc[c][j];
}

extern "C" void kernel_launch(void* const* d_in, const int* in_sizes, int n_in,
                              void* d_out, int out_size)
{
    const float* x = (const float*)d_in[0];
    const float* f = (const float*)d_in[1];
    float* out = (float*)d_out;

    dim3 grid(T_DIM * H_DIM);   // 3200 blocks: one per (t, h) row
    dim3 block(128);
    duf_kernel<<<grid, block>>>(x, f, out);
}

// round 5
// speedup vs baseline: 1.0704x; 1.0704x over previous
#include <cuda_runtime.h>

// DynamicUpsamplingFilter:
//   x:       (1, 3, 25, 128, 128) float32          -> d_in[0]
//   filters: (1, 25, 16, 25, 128, 128) float32     -> d_in[1]
//   out:     (1, 48, 25, 128, 128) float32
// out[c*16+u, t, h, w] = sum_{a,b} x[c, t, h+a-2, w+b-2] * filters[a*5+b, u, t, h, w]
//
// R5: float4 filter loads + conflict-free float4 window LDS (R4) combined with
// u-split (8 u per block, 2 per thread) to cut accumulator registers in half
// and raise occupancy to ~7 CTAs/SM (28 warps).

#define T_DIM 25
#define H_DIM 128
#define W_DIM 128
#define HW    (H_DIM * W_DIM)       // 16384
#define THW   (T_DIM * HW)          // 409600
#define C_IN  3
#define KH    5
#define KW    5
#define UPSQ  16
#define UG    2                     // u per thread

__global__ __launch_bounds__(128, 7)
void duf_kernel(const float* __restrict__ x,
                const float* __restrict__ f,
                float* __restrict__ out)
{
    const int tid = threadIdx.x;
    const int w4  = tid & 31;            // float4 index over w
    const int ug  = tid >> 5;            // 0..3
    const int w0  = w4 << 2;
    const int h = blockIdx.x & (H_DIM - 1);
    const int t = blockIdx.x >> 7;
    const int u0 = blockIdx.y * 8 + ug * UG;   // first u of this thread

    // x patch tile: 3 channels x 5 rows x (128 + 4) cols, zero halo in w.
    __shared__ __align__(16) float sx[C_IN][KH][W_DIM + 4];

    if (tid < 2) {
        #pragma unroll
        for (int c = 0; c < C_IN; c++)
            #pragma unroll
            for (int a = 0; a < KH; a++) {
                sx[c][a][tid] = 0.0f;
                sx[c][a][W_DIM + 2 + tid] = 0.0f;
            }
    }

    // stage x rows h-2..h+2 for all 3 channels (tid = w index here)
    #pragma unroll
    for (int c = 0; c < C_IN; c++) {
        #pragma unroll
        for (int a = 0; a < KH; a++) {
            const int hh = h + a - 2;
            float v = 0.0f;
            if (hh >= 0 && hh < H_DIM)
                v = __ldg(&x[c * THW + t * HW + hh * W_DIM + tid]);
            sx[c][a][tid + 2] = v;
        }
    }
    __syncthreads();

    const int rowbase = t * HW + h * W_DIM;
    // filter pointer for (k=0, u=u0, this row, w0)
    const float4* fp = (const float4*)(f + (size_t)u0 * THW + rowbase + w0);

    float4 acc[C_IN][UG];
    #pragma unroll
    for (int c = 0; c < C_IN; c++)
        #pragma unroll
        for (int j = 0; j < UG; j++)
            acc[c][j] = make_float4(0.f, 0.f, 0.f, 0.f);

    #pragma unroll 1
    for (int a = 0; a < KH; a++) {
        // conflict-free window: 8 floats per channel as two aligned LDS.128
        float win[C_IN][8];
        #pragma unroll
        for (int c = 0; c < C_IN; c++) {
            const float4 lo = *(const float4*)&sx[c][a][w0];
            const float4 hi = *(const float4*)&sx[c][a][w0 + 4];
            win[c][0] = lo.x; win[c][1] = lo.y; win[c][2] = lo.z; win[c][3] = lo.w;
            win[c][4] = hi.x; win[c][5] = hi.y; win[c][6] = hi.z; win[c][7] = hi.w;
        }

        const float4* fa = fp + (size_t)(a * KW) * (UPSQ * THW / 4);

        #pragma unroll
        for (int b = 0; b < KW; b++) {
            const float4* fk = fa + (size_t)b * (UPSQ * THW / 4);
            float4 fv[UG];
            #pragma unroll
            for (int j = 0; j < UG; j++)
                fv[j] = __ldg(fk + (size_t)j * (THW / 4));

            #pragma unroll
            for (int c = 0; c < C_IN; c++) {
                const float p0 = win[c][b];
                const float p1 = win[c][b + 1];
                const float p2 = win[c][b + 2];
                const float p3 = win[c][b + 3];
                #pragma unroll
                for (int j = 0; j < UG; j++) {
                    acc[c][j].x = fmaf(p0, fv[j].x, acc[c][j].x);
                    acc[c][j].y = fmaf(p1, fv[j].y, acc[c][j].y);
                    acc[c][j].z = fmaf(p2, fv[j].z, acc[c][j].z);
                    acc[c][j].w = fmaf(p3, fv[j].w, acc[c][j].w);
                }
            }
        }
    }

    // out[(c*16 + u0 + j)*THW + rowbase + w0], 512B/warp stores
    float4* op = (float4*)(out + (size_t)u0 * THW + rowbase + w0);
    #pragma unroll
    for (int c = 0; c < C_IN; c++)
        #pragma unroll
        for (int j = 0; j < UG; j++)
            op[((size_t)c * UPSQ + j) * (THW / 4)] = acc[c][j];
}

extern "C" void kernel_launch(void* const* d_in, const int* in_sizes, int n_in,
                              void* d_out, int out_size)
{
    const float* x = (const float*)d_in[0];
    const float* f = (const float*)d_in[1];
    float* out = (float*)d_out;

    dim3 grid(T_DIM * H_DIM, 2);  // (t*h row, u-half)
    dim3 block(128);
    duf_kernel<<<grid, block>>>(x, f, out);
}